// round 14
// baseline (speedup 1.0000x reference)
#include <cuda_runtime.h>
#include <cuda_fp16.h>
#include <cstdint>

#define B_ 2048
#define NT 384

// ---- SMEM (bytes), 112KB/CTA, 2 CTAs/SM -----------------------------------
// proj: X fp16 [128][256] swizzled 512B rows @0 (64KB)
//       W db: 2 x [3][64 n][64 k] fp16 128B rows @65536 (2 x 24KB)
// attn overlay (X region dead after proj): K @0, V @16384, Q @32768
#define SM_X   0
#define SM_WDB 65536
#define SM_K   0
#define SM_V   16384
#define SM_Q   32768
#define SMEM_BYTES 114688

__device__ __half g_Wt[3 * 64 * 256];   // W^T fp16 [m][h][c], Q pre-scaled

// ---- PTX helpers ----------------------------------------------------------
__device__ __forceinline__ uint32_t smem_u32(const void* p) {
    uint32_t a;
    asm("{ .reg .u64 t; cvta.to.shared.u64 t, %1; cvt.u32.u64 %0, t; }"
        : "=r"(a) : "l"(p));
    return a;
}
__device__ __forceinline__ void ldm4(uint32_t* r, uint32_t addr) {
    asm volatile("ldmatrix.sync.aligned.m8n8.x4.shared.b16 {%0,%1,%2,%3}, [%4];"
                 : "=r"(r[0]), "=r"(r[1]), "=r"(r[2]), "=r"(r[3]) : "r"(addr));
}
__device__ __forceinline__ void ldm4t(uint32_t* r, uint32_t addr) {
    asm volatile("ldmatrix.sync.aligned.m8n8.x4.trans.shared.b16 {%0,%1,%2,%3}, [%4];"
                 : "=r"(r[0]), "=r"(r[1]), "=r"(r[2]), "=r"(r[3]) : "r"(addr));
}
__device__ __forceinline__ void mma16816(float* d, const uint32_t* a,
                                         uint32_t b0, uint32_t b1) {
    asm("mma.sync.aligned.m16n8k16.row.col.f32.f16.f16.f32 "
        "{%0,%1,%2,%3}, {%4,%5,%6,%7}, {%8,%9}, {%0,%1,%2,%3};"
        : "+f"(d[0]), "+f"(d[1]), "+f"(d[2]), "+f"(d[3])
        : "r"(a[0]), "r"(a[1]), "r"(a[2]), "r"(a[3]), "r"(b0), "r"(b1));
}
__device__ __forceinline__ uint32_t pack_h2(float a, float b) {
    uint32_t r;
    asm("cvt.rn.f16x2.f32 %0, %1, %2;" : "=r"(r) : "f"(b), "f"(a));
    return r;
}
__device__ __forceinline__ float ex2(float x) {
    float r;
    asm("ex2.approx.f32 %0, %1;" : "=f"(r) : "f"(x));
    return r;
}
__device__ __forceinline__ void cp16(uint32_t sdst, const void* gsrc) {
    asm volatile("cp.async.cg.shared.global [%0], [%1], 16;"
                 :: "r"(sdst), "l"(gsrc));
}
#define CP_COMMIT()  asm volatile("cp.async.commit_group;" ::: "memory")
#define CP_WAIT(n)   asm volatile("cp.async.wait_group %0;" :: "n"(n) : "memory")
#define SWC(chunk, row) ((((chunk) ^ ((row) & 7)) << 4))

// ---- prep kernel: W[c][h] fp32 -> W^T[h][c] fp16; Q scale folded ----------
__global__ void prep_w(const float* __restrict__ Wk,
                       const float* __restrict__ Wq,
                       const float* __restrict__ Wv)
{
    int idx = blockIdx.x * 256 + threadIdx.x;
    int m = idx >> 14;
    int r = idx & 16383;
    int h = r >> 8, c = r & 255;
    const float* W = (m == 0) ? Wk : ((m == 1) ? Wq : Wv);
    float s = (m == 1) ? 0.09016844f : 1.0f;   // 2^-4 * log2(e) folded into Wq
    g_Wt[idx] = __float2half_rn(W[c * 64 + h] * s);
}

// stage W k-chunk kc (64 k-cols, all 3 matrices) into buffer bsel: 4/thread
__device__ __forceinline__ void stage_w(uint32_t smb, int tid, int kc, int bsel) {
#pragma unroll
    for (int t = 0; t < 4; t++) {
        int idx = tid + t * NT;          // 1536 16B units
        int m = idx >> 9;
        int rem = idx & 511;
        int n = rem >> 3, j = rem & 7;
        cp16(smb + SM_WDB + bsel * 24576 + m * 8192 + n * 128 + SWC(j, n),
             g_Wt + m * 16384 + n * 256 + kc * 64 + j * 8);
    }
    CP_COMMIT();
}

// ---- main kernel ----------------------------------------------------------
__global__ void __launch_bounds__(NT, 2)
head_mma(const float* __restrict__ x, float* __restrict__ out)
{
    extern __shared__ char sm[];
    const uint32_t smb = smem_u32(sm);
    const int tid = threadIdx.x, lane = tid & 31, wid = tid >> 5;
    const float* xb = x + (size_t)blockIdx.x * (128 * 256);

    // ---- prologue: W chunk0 cp.async, then X full staging (overlapped) ----
    stage_w(smb, tid, 0, 0);
    for (int u = tid; u < 8192; u += NT) {           // 8192 float4
        int row = u >> 6, cp4 = u & 63;
        float4 v = *(const float4*)(xb + 4 * u);
        uint2 pk = make_uint2(pack_h2(v.x, v.y), pack_h2(v.z, v.w));
        uint32_t off = row * 512 + SWC(cp4 >> 1, row) + ((cp4 & 1) << 3);
        *(uint2*)(sm + SM_X + off) = pk;
    }
    CP_WAIT(0);
    __syncthreads();

    // ================= Phase 1: projections (warp owns one matrix) ========
    const int m3 = wid >> 2;            // 0=K,1=Q,2=V
    const int mr = (wid & 3) * 32;      // warp M-block
    float pacc[2][8][4];
#pragma unroll
    for (int mt = 0; mt < 2; mt++)
#pragma unroll
        for (int nt = 0; nt < 8; nt++)
#pragma unroll
            for (int i = 0; i < 4; i++) pacc[mt][nt][i] = 0.f;

#pragma unroll
    for (int kc = 0; kc < 4; kc++) {
        if (kc < 3) stage_w(smb, tid, kc + 1, (kc + 1) & 1);
        if (kc) {
            if (kc < 3) CP_WAIT(1); else CP_WAIT(0);
            __syncthreads();            // kc's data visible to all
        }
        uint32_t wb = smb + SM_WDB + (kc & 1) * 24576 + m3 * 8192;
#pragma unroll
        for (int ks = 0; ks < 4; ks++) {
            int k16 = kc * 4 + ks;
            uint32_t ah[2][4];
#pragma unroll
            for (int mt = 0; mt < 2; mt++) {
                int ar = mr + 16 * mt + (lane & 15);
                ldm4(ah[mt], smb + SM_X + ar * 512
                             + SWC(2 * k16 + (lane >> 4), ar));
            }
#pragma unroll
            for (int n16 = 0; n16 < 4; n16++) {
                uint32_t bh[4];
                int bn = 16 * n16 + ((lane >> 3) & 1) * 8 + (lane & 7);
                ldm4(bh, wb + bn * 128 + SWC(2 * ks + (lane >> 4), bn));
#pragma unroll
                for (int mt = 0; mt < 2; mt++)
#pragma unroll
                    for (int j = 0; j < 2; j++)
                        mma16816(pacc[mt][2 * n16 + j],
                                 ah[mt], bh[j], bh[j + 2]);
            }
        }
        if (kc < 3) __syncthreads();    // readers done before buffer overwrite
    }
    __syncthreads();                    // X reads done; overlay spill tiles

    // ---- spill K/Q/V fp16 tiles [row][h] (scales pre-folded) -------------
    {
        uint32_t base = (m3 == 0) ? SM_K : ((m3 == 1) ? SM_Q : SM_V);
#pragma unroll
        for (int mt = 0; mt < 2; mt++)
#pragma unroll
            for (int nt = 0; nt < 8; nt++) {
                float* d = pacc[mt][nt];
                int sra = mr + 16 * mt + (lane >> 2), srb = sra + 8;
                int c = 8 * nt + 2 * (lane & 3);
                uint32_t o0 = sra * 128 + SWC(c >> 3, sra) + ((c & 7) << 1);
                uint32_t o1 = srb * 128 + SWC(c >> 3, srb) + ((c & 7) << 1);
                *(uint32_t*)(sm + base + o0) = pack_h2(d[0], d[1]);
                *(uint32_t*)(sm + base + o1) = pack_h2(d[2], d[3]);
            }
    }
    __syncthreads();

    // ============ Phase 2: flash attention (warps 0-7) =====================
    if (wid < 8) {
        // SMSP-balanced strips: warps 0..3 -> 0..3, warps 4..7 -> 7,6,5,4
        const int sw = (wid < 4) ? wid : (11 - wid);
        const int r16 = sw * 16;
        const int ra = r16 + (lane >> 2), rb = ra + 8;

        uint32_t qf[4][4];
#pragma unroll
        for (int ks = 0; ks < 4; ks++) {
            int qr = r16 + (lane & 15);
            ldm4(qf[ks], smb + SM_Q + qr * 128 + SWC(2 * ks + (lane >> 4), qr));
        }

        float m0 = -1e30f, m1 = -1e30f, l0 = 0.f, l1 = 0.f;
        float oacc[8][4];
#pragma unroll
        for (int nt = 0; nt < 8; nt++)
#pragma unroll
            for (int i = 0; i < 4; i++) oacc[nt][i] = 0.f;

        const int cmax = (sw < 4) ? 1 : 2;
        for (int c = 0; c < cmax; c++) {
            float sacc[8][4];
#pragma unroll
            for (int nt = 0; nt < 8; nt++)
#pragma unroll
                for (int i = 0; i < 4; i++) sacc[nt][i] = 0.f;

#pragma unroll
            for (int ks = 0; ks < 4; ks++) {
#pragma unroll
                for (int n16 = 0; n16 < 4; n16++) {
                    if (4 * c + n16 <= sw) {
                        int bn = 64 * c + 16 * n16
                               + ((lane >> 3) & 1) * 8 + (lane & 7);
                        uint32_t kh[4];
                        ldm4(kh, smb + SM_K + bn * 128
                                 + SWC(2 * ks + (lane >> 4), bn));
#pragma unroll
                        for (int j = 0; j < 2; j++)
                            mma16816(sacc[2 * n16 + j], qf[ks],
                                     kh[j], kh[j + 2]);
                    }
                }
            }

            // causal mask + chunk max
            float cm0 = -1e30f, cm1 = -1e30f;
            if (64 * c + 64 <= r16) {
#pragma unroll
                for (int nt = 0; nt < 8; nt++) {
                    cm0 = fmaxf(cm0, fmaxf(sacc[nt][0], sacc[nt][1]));
                    cm1 = fmaxf(cm1, fmaxf(sacc[nt][2], sacc[nt][3]));
                }
            } else {
#pragma unroll
                for (int nt = 0; nt < 8; nt++) {
                    bool act = (4 * c + (nt >> 1)) <= sw;
                    int s0 = 64 * c + 8 * nt + 2 * (lane & 3);
                    float v0 = (act && s0 <= ra)     ? sacc[nt][0] : -1e30f;
                    float v1 = (act && s0 + 1 <= ra) ? sacc[nt][1] : -1e30f;
                    float v2 = (act && s0 <= rb)     ? sacc[nt][2] : -1e30f;
                    float v3 = (act && s0 + 1 <= rb) ? sacc[nt][3] : -1e30f;
                    sacc[nt][0] = v0; sacc[nt][1] = v1;
                    sacc[nt][2] = v2; sacc[nt][3] = v3;
                    cm0 = fmaxf(cm0, fmaxf(v0, v1));
                    cm1 = fmaxf(cm1, fmaxf(v2, v3));
                }
            }
            cm0 = fmaxf(cm0, __shfl_xor_sync(0xFFFFFFFFu, cm0, 1));
            cm0 = fmaxf(cm0, __shfl_xor_sync(0xFFFFFFFFu, cm0, 2));
            cm1 = fmaxf(cm1, __shfl_xor_sync(0xFFFFFFFFu, cm1, 1));
            cm1 = fmaxf(cm1, __shfl_xor_sync(0xFFFFFFFFu, cm1, 2));

            float mn0 = fmaxf(m0, cm0), mn1 = fmaxf(m1, cm1);
            float a0 = ex2(m0 - mn0), a1 = ex2(m1 - mn1);
            float cs0 = 0.f, cs1 = 0.f;
#pragma unroll
            for (int nt = 0; nt < 8; nt++) {
                float e0 = ex2(sacc[nt][0] - mn0);
                float e1 = ex2(sacc[nt][1] - mn0);
                float e2 = ex2(sacc[nt][2] - mn1);
                float e3 = ex2(sacc[nt][3] - mn1);
                sacc[nt][0] = e0; sacc[nt][1] = e1;
                sacc[nt][2] = e2; sacc[nt][3] = e3;
                cs0 += e0 + e1;
                cs1 += e2 + e3;
            }
            cs0 += __shfl_xor_sync(0xFFFFFFFFu, cs0, 1);
            cs0 += __shfl_xor_sync(0xFFFFFFFFu, cs0, 2);
            cs1 += __shfl_xor_sync(0xFFFFFFFFu, cs1, 1);
            cs1 += __shfl_xor_sync(0xFFFFFFFFu, cs1, 2);
            l0 = l0 * a0 + cs0;
            l1 = l1 * a1 + cs1;
            m0 = mn0; m1 = mn1;

#pragma unroll
            for (int nt = 0; nt < 8; nt++) {
                oacc[nt][0] *= a0; oacc[nt][1] *= a0;
                oacc[nt][2] *= a1; oacc[nt][3] *= a1;
            }

            // O += P_chunk @ V_chunk (P packed from sacc in registers)
#pragma unroll
            for (int ks2 = 0; ks2 < 4; ks2++) {
                if (4 * c + ks2 <= sw) {
                    uint32_t pa[4];
                    pa[0] = pack_h2(sacc[2 * ks2][0], sacc[2 * ks2][1]);
                    pa[1] = pack_h2(sacc[2 * ks2][2], sacc[2 * ks2][3]);
                    pa[2] = pack_h2(sacc[2 * ks2 + 1][0], sacc[2 * ks2 + 1][1]);
                    pa[3] = pack_h2(sacc[2 * ks2 + 1][2], sacc[2 * ks2 + 1][3]);
#pragma unroll
                    for (int ntv = 0; ntv < 4; ntv++) {
                        int vr = 64 * c + 16 * ks2 + (lane & 15);
                        uint32_t vh[4];
                        ldm4t(vh, smb + SM_V + vr * 128
                                  + SWC(2 * ntv + (lane >> 4), vr));
#pragma unroll
                        for (int j = 0; j < 2; j++)
                            mma16816(oacc[2 * ntv + j],
                                     pa, vh[2 * j], vh[2 * j + 1]);
                    }
                }
            }
        }

        // normalize + write out
        float inv0 = 1.f / l0, inv1 = 1.f / l1;
        float* ob = out + (size_t)blockIdx.x * (128 * 64);
#pragma unroll
        for (int nt = 0; nt < 8; nt++) {
            int c0 = 8 * nt + 2 * (lane & 3);
            *(float2*)(ob + ra * 64 + c0) =
                make_float2(oacc[nt][0] * inv0, oacc[nt][1] * inv0);
            *(float2*)(ob + rb * 64 + c0) =
                make_float2(oacc[nt][2] * inv1, oacc[nt][3] * inv1);
        }
    }
}

extern "C" void kernel_launch(void* const* d_in, const int* in_sizes, int n_in,
                              void* d_out, int out_size) {
    const float* x  = (const float*)d_in[0];
    const float* Wk = (const float*)d_in[1];
    const float* Wq = (const float*)d_in[2];
    const float* Wv = (const float*)d_in[3];
    float* out = (float*)d_out;

    prep_w<<<192, 256>>>(Wk, Wq, Wv);

    cudaFuncSetAttribute(head_mma,
                         cudaFuncAttributeMaxDynamicSharedMemorySize,
                         SMEM_BYTES);
    head_mma<<<B_, NT, SMEM_BYTES>>>(x, out);
}

// round 15
// speedup vs baseline: 2.1410x; 2.1410x over previous
#include <cuda_runtime.h>
#include <cuda_fp16.h>
#include <cstdint>

#define B_ 2048
#define NT 256

// ---- SMEM (bytes), 112KB/CTA, 2 CTAs/SM -----------------------------------
// proj: X fp16 [128][256] swizzled 512B rows @0 (64KB)
//       W db: 2 x [3][64 n][64 k] fp16 128B rows @65536 (2 x 24KB)
// attn overlay (X region dead after proj): K @0, V @16384, Q @32768
#define SM_X   0
#define SM_WDB 65536
#define SM_K   0
#define SM_V   16384
#define SM_Q   32768
#define SMEM_BYTES 114688

__device__ __half g_Wt[3 * 64 * 256];   // W^T fp16 [m][h][c], Q pre-scaled

// ---- PTX helpers ----------------------------------------------------------
__device__ __forceinline__ uint32_t smem_u32(const void* p) {
    uint32_t a;
    asm("{ .reg .u64 t; cvta.to.shared.u64 t, %1; cvt.u32.u64 %0, t; }"
        : "=r"(a) : "l"(p));
    return a;
}
__device__ __forceinline__ void ldm4(uint32_t* r, uint32_t addr) {
    asm volatile("ldmatrix.sync.aligned.m8n8.x4.shared.b16 {%0,%1,%2,%3}, [%4];"
                 : "=r"(r[0]), "=r"(r[1]), "=r"(r[2]), "=r"(r[3]) : "r"(addr));
}
__device__ __forceinline__ void ldm4t(uint32_t* r, uint32_t addr) {
    asm volatile("ldmatrix.sync.aligned.m8n8.x4.trans.shared.b16 {%0,%1,%2,%3}, [%4];"
                 : "=r"(r[0]), "=r"(r[1]), "=r"(r[2]), "=r"(r[3]) : "r"(addr));
}
__device__ __forceinline__ void mma16816(float* d, const uint32_t* a,
                                         uint32_t b0, uint32_t b1) {
    asm("mma.sync.aligned.m16n8k16.row.col.f32.f16.f16.f32 "
        "{%0,%1,%2,%3}, {%4,%5,%6,%7}, {%8,%9}, {%0,%1,%2,%3};"
        : "+f"(d[0]), "+f"(d[1]), "+f"(d[2]), "+f"(d[3])
        : "r"(a[0]), "r"(a[1]), "r"(a[2]), "r"(a[3]), "r"(b0), "r"(b1));
}
__device__ __forceinline__ uint32_t pack_h2(float a, float b) {
    uint32_t r;
    asm("cvt.rn.f16x2.f32 %0, %1, %2;" : "=r"(r) : "f"(b), "f"(a));
    return r;
}
__device__ __forceinline__ float ex2(float x) {
    float r;
    asm("ex2.approx.f32 %0, %1;" : "=f"(r) : "f"(x));
    return r;
}
__device__ __forceinline__ void cp16(uint32_t sdst, const void* gsrc) {
    asm volatile("cp.async.cg.shared.global [%0], [%1], 16;"
                 :: "r"(sdst), "l"(gsrc));
}
#define CP_COMMIT()  asm volatile("cp.async.commit_group;" ::: "memory")
#define CP_WAIT(n)   asm volatile("cp.async.wait_group %0;" :: "n"(n) : "memory")
#define SWC(chunk, row) ((((chunk) ^ ((row) & 7)) << 4))

// ---- prep kernel: W[c][h] fp32 -> W^T[h][c] fp16; Q scale folded ----------
__global__ void prep_w(const float* __restrict__ Wk,
                       const float* __restrict__ Wq,
                       const float* __restrict__ Wv)
{
    int idx = blockIdx.x * 256 + threadIdx.x;
    int m = idx >> 14;
    int r = idx & 16383;
    int h = r >> 8, c = r & 255;
    const float* W = (m == 0) ? Wk : ((m == 1) ? Wq : Wv);
    float s = (m == 1) ? 0.09016844f : 1.0f;   // 2^-4 * log2(e) into Wq
    g_Wt[idx] = __float2half_rn(W[c * 64 + h] * s);
}

// stage W k-chunk kc (64 k-cols, all 3 matrices) into buffer bsel: 6/thread
__device__ __forceinline__ void stage_w(uint32_t smb, int tid, int kc, int bsel) {
#pragma unroll
    for (int t = 0; t < 6; t++) {
        int idx = tid + t * NT;          // 1536 16B units
        int m = idx >> 9;
        int rem = idx & 511;
        int n = rem >> 3, j = rem & 7;
        cp16(smb + SM_WDB + bsel * 24576 + m * 8192 + n * 128 + SWC(j, n),
             g_Wt + m * 16384 + n * 256 + kc * 64 + j * 8);
    }
    CP_COMMIT();
}

// ---- main kernel ----------------------------------------------------------
__global__ void __launch_bounds__(NT, 2)
head_mma(const float* __restrict__ x, float* __restrict__ out)
{
    extern __shared__ char sm[];
    const uint32_t smb = smem_u32(sm);
    const int tid = threadIdx.x, lane = tid & 31, wid = tid >> 5;
    const float* xb = x + (size_t)blockIdx.x * (128 * 256);

    // ---- prologue: W chunk0 cp.async, then full X staging (overlapped) ----
    stage_w(smb, tid, 0, 0);

    // X [128][256] fp32 -> fp16 swizzled, 512B rows (float4 loads, STS.64)
#pragma unroll 8
    for (int it = 0; it < 32; it++) {
        int u = tid + (it << 8);          // float4 index, 8192 total
        int row = u >> 6, cp4 = u & 63;
        float4 v = *(const float4*)(xb + 4 * u);
        uint2 pk = make_uint2(pack_h2(v.x, v.y), pack_h2(v.z, v.w));
        uint32_t off = row * 512 + SWC(cp4 >> 1, row) + ((cp4 & 1) << 3);
        *(uint2*)(sm + SM_X + off) = pk;
    }
    CP_WAIT(0);
    __syncthreads();

    // ================= Phase 1: QKV projections (R10 tile, W db) ===========
    float pacc[3][2][4][4];
#pragma unroll
    for (int m = 0; m < 3; m++)
#pragma unroll
        for (int mt = 0; mt < 2; mt++)
#pragma unroll
            for (int nt = 0; nt < 4; nt++)
#pragma unroll
                for (int i = 0; i < 4; i++) pacc[m][mt][nt][i] = 0.f;

    const int mr = (wid & 3) * 32;      // warp M-block (rows)
    const int nc = (wid >> 2) * 32;     // warp N-block (cols within matrix)

#pragma unroll
    for (int kc = 0; kc < 4; kc++) {
        if (kc < 3) stage_w(smb, tid, kc + 1, (kc + 1) & 1);   // prefetch
        const uint32_t wb = smb + SM_WDB + (kc & 1) * 24576;
#pragma unroll 2
        for (int ks = 0; ks < 4; ks++) {
            int k16 = kc * 4 + ks;
            uint32_t ah[2][4];
#pragma unroll
            for (int mt = 0; mt < 2; mt++) {
                int ar = mr + 16 * mt + (lane & 15);
                ldm4(ah[mt], smb + SM_X + ar * 512
                             + SWC(2 * k16 + (lane >> 4), ar));
            }
#pragma unroll
            for (int m = 0; m < 3; m++) {
#pragma unroll
                for (int n16 = 0; n16 < 2; n16++) {
                    uint32_t bh[4];
                    int bn = nc + 16 * n16 + ((lane >> 3) & 1) * 8 + (lane & 7);
                    ldm4(bh, wb + m * 8192 + bn * 128
                             + SWC(2 * ks + (lane >> 4), bn));
#pragma unroll
                    for (int mt = 0; mt < 2; mt++)
#pragma unroll
                        for (int j = 0; j < 2; j++)
                            mma16816(pacc[m][mt][2 * n16 + j],
                                     ah[mt], bh[j], bh[j + 2]);
                }
            }
        }
        if (kc < 3) {
            CP_WAIT(0);        // next chunk landed (hidden behind compute)
            __syncthreads();   // all readers of old buffer done
        }
    }
    __syncthreads();   // proj MMAs done; overlay attn region onto X

    // ---- spill K/Q/V fp16 tiles [row][h] (Q scale pre-folded) -------------
#pragma unroll
    for (int m = 0; m < 3; m++) {
        uint32_t base = (m == 0) ? SM_K : ((m == 1) ? SM_Q : SM_V);
#pragma unroll
        for (int mt = 0; mt < 2; mt++)
#pragma unroll
            for (int nt = 0; nt < 4; nt++) {
                float* d = pacc[m][mt][nt];
                int sra = mr + 16 * mt + (lane >> 2), srb = sra + 8;
                int c = nc + 8 * nt + 2 * (lane & 3);
                uint32_t o0 = sra * 128 + SWC(c >> 3, sra) + ((c & 7) << 1);
                uint32_t o1 = srb * 128 + SWC(c >> 3, srb) + ((c & 7) << 1);
                *(uint32_t*)(sm + base + o0) = pack_h2(d[0], d[1]);
                *(uint32_t*)(sm + base + o1) = pack_h2(d[2], d[3]);
            }
    }
    __syncthreads();

    // ---- SMSP-balanced strip map: SMSP s gets strips s and 7-s -----------
    const int sw = (wid < 4) ? wid : (11 - wid);
    const int r16 = sw * 16;

    // ---- load Q fragments into registers ---------------------------------
    uint32_t qf[4][4];
#pragma unroll
    for (int ks = 0; ks < 4; ks++) {
        int ar = r16 + (lane & 15);
        ldm4(qf[ks], smb + SM_Q + ar * 128 + SWC(2 * ks + (lane >> 4), ar));
    }

    // ============ Phase 2: flash attention, exp2 domain, P in regs =========
    const int ra = r16 + (lane >> 2), rb = ra + 8;
    float m0 = -1e30f, m1 = -1e30f, l0 = 0.f, l1 = 0.f;
    float oacc[8][4];
#pragma unroll
    for (int nt = 0; nt < 8; nt++)
#pragma unroll
        for (int i = 0; i < 4; i++) oacc[nt][i] = 0.f;

    const int cmax = (sw < 4) ? 1 : 2;
    for (int c = 0; c < cmax; c++) {
        float sacc[8][4];
#pragma unroll
        for (int nt = 0; nt < 8; nt++)
#pragma unroll
            for (int i = 0; i < 4; i++) sacc[nt][i] = 0.f;

#pragma unroll
        for (int ks = 0; ks < 4; ks++) {
#pragma unroll
            for (int n16 = 0; n16 < 4; n16++) {
                if (4 * c + n16 <= sw) {
                    int bn = 64 * c + 16 * n16
                           + ((lane >> 3) & 1) * 8 + (lane & 7);
                    uint32_t kh[4];
                    ldm4(kh, smb + SM_K + bn * 128
                             + SWC(2 * ks + (lane >> 4), bn));
#pragma unroll
                    for (int j = 0; j < 2; j++)
                        mma16816(sacc[2 * n16 + j], qf[ks], kh[j], kh[j + 2]);
                }
            }
        }

        // ---- causal mask + chunk max ----
        float cm0 = -1e30f, cm1 = -1e30f;
        if (64 * c + 64 <= r16) {       // fully below diagonal
#pragma unroll
            for (int nt = 0; nt < 8; nt++) {
                cm0 = fmaxf(cm0, fmaxf(sacc[nt][0], sacc[nt][1]));
                cm1 = fmaxf(cm1, fmaxf(sacc[nt][2], sacc[nt][3]));
            }
        } else {
#pragma unroll
            for (int nt = 0; nt < 8; nt++) {
                bool act = (4 * c + (nt >> 1)) <= sw;
                int s0 = 64 * c + 8 * nt + 2 * (lane & 3);
                float v0 = (act && s0 <= ra)     ? sacc[nt][0] : -1e30f;
                float v1 = (act && s0 + 1 <= ra) ? sacc[nt][1] : -1e30f;
                float v2 = (act && s0 <= rb)     ? sacc[nt][2] : -1e30f;
                float v3 = (act && s0 + 1 <= rb) ? sacc[nt][3] : -1e30f;
                sacc[nt][0] = v0; sacc[nt][1] = v1;
                sacc[nt][2] = v2; sacc[nt][3] = v3;
                cm0 = fmaxf(cm0, fmaxf(v0, v1));
                cm1 = fmaxf(cm1, fmaxf(v2, v3));
            }
        }
        cm0 = fmaxf(cm0, __shfl_xor_sync(0xFFFFFFFFu, cm0, 1));
        cm0 = fmaxf(cm0, __shfl_xor_sync(0xFFFFFFFFu, cm0, 2));
        cm1 = fmaxf(cm1, __shfl_xor_sync(0xFFFFFFFFu, cm1, 1));
        cm1 = fmaxf(cm1, __shfl_xor_sync(0xFFFFFFFFu, cm1, 2));

        float mn0 = fmaxf(m0, cm0), mn1 = fmaxf(m1, cm1);
        float a0 = ex2(m0 - mn0), a1 = ex2(m1 - mn1);
        float cs0 = 0.f, cs1 = 0.f;
#pragma unroll
        for (int nt = 0; nt < 8; nt++) {
            float e0 = ex2(sacc[nt][0] - mn0);
            float e1 = ex2(sacc[nt][1] - mn0);
            float e2 = ex2(sacc[nt][2] - mn1);
            float e3 = ex2(sacc[nt][3] - mn1);
            sacc[nt][0] = e0; sacc[nt][1] = e1;
            sacc[nt][2] = e2; sacc[nt][3] = e3;
            cs0 += e0 + e1;
            cs1 += e2 + e3;
        }
        cs0 += __shfl_xor_sync(0xFFFFFFFFu, cs0, 1);
        cs0 += __shfl_xor_sync(0xFFFFFFFFu, cs0, 2);
        cs1 += __shfl_xor_sync(0xFFFFFFFFu, cs1, 1);
        cs1 += __shfl_xor_sync(0xFFFFFFFFu, cs1, 2);
        l0 = l0 * a0 + cs0;
        l1 = l1 * a1 + cs1;
        m0 = mn0; m1 = mn1;

#pragma unroll
        for (int nt = 0; nt < 8; nt++) {
            oacc[nt][0] *= a0; oacc[nt][1] *= a0;
            oacc[nt][2] *= a1; oacc[nt][3] *= a1;
        }

        // ---- O += P_chunk @ V_chunk (P packed from sacc in registers) ----
#pragma unroll
        for (int ks2 = 0; ks2 < 4; ks2++) {
            if (4 * c + ks2 <= sw) {
                uint32_t pa[4];
                pa[0] = pack_h2(sacc[2 * ks2][0], sacc[2 * ks2][1]);
                pa[1] = pack_h2(sacc[2 * ks2][2], sacc[2 * ks2][3]);
                pa[2] = pack_h2(sacc[2 * ks2 + 1][0], sacc[2 * ks2 + 1][1]);
                pa[3] = pack_h2(sacc[2 * ks2 + 1][2], sacc[2 * ks2 + 1][3]);
#pragma unroll
                for (int ntv = 0; ntv < 4; ntv++) {
                    int vr = 64 * c + 16 * ks2 + (lane & 15);
                    uint32_t vh[4];
                    ldm4t(vh, smb + SM_V + vr * 128
                              + SWC(2 * ntv + (lane >> 4), vr));
#pragma unroll
                    for (int j = 0; j < 2; j++)
                        mma16816(oacc[2 * ntv + j],
                                 pa, vh[2 * j], vh[2 * j + 1]);
                }
            }
        }
    }

    // ---- normalize + write out -------------------------------------------
    float inv0 = 1.f / l0, inv1 = 1.f / l1;
    float* ob = out + (size_t)blockIdx.x * (128 * 64);
#pragma unroll
    for (int nt = 0; nt < 8; nt++) {
        int c0 = 8 * nt + 2 * (lane & 3);
        *(float2*)(ob + ra * 64 + c0) =
            make_float2(oacc[nt][0] * inv0, oacc[nt][1] * inv0);
        *(float2*)(ob + rb * 64 + c0) =
            make_float2(oacc[nt][2] * inv1, oacc[nt][3] * inv1);
    }
}

extern "C" void kernel_launch(void* const* d_in, const int* in_sizes, int n_in,
                              void* d_out, int out_size) {
    const float* x  = (const float*)d_in[0];
    const float* Wk = (const float*)d_in[1];
    const float* Wq = (const float*)d_in[2];
    const float* Wv = (const float*)d_in[3];
    float* out = (float*)d_out;

    prep_w<<<192, 256>>>(Wk, Wq, Wv);

    cudaFuncSetAttribute(head_mma,
                         cudaFuncAttributeMaxDynamicSharedMemorySize,
                         SMEM_BYTES);
    head_mma<<<B_, NT, SMEM_BYTES>>>(x, out);
}